// round 10
// baseline (speedup 1.0000x reference)
#include <cuda_runtime.h>
#include <cuda_fp16.h>
#include <mma.h>
#include <math.h>

using namespace nvcuda;

#define NN 50000
#define EE 1600000
#define HH 64
#define FIN 8
#define PP 5
#define LL 3
#define CI 68   // H + 4
#define SCAN_BLK 256
#define NBLK ((NN + SCAN_BLK - 1) / SCAN_BLK)   // 196
#define NSLOT 64

// ---------------- scratch (device globals; no allocation) ----------------
__device__ __align__(128) float g_deg[NN];
__device__ __align__(128) float g_dis[NN];
__device__ __align__(128) int   g_cnt[NN];
__device__ __align__(128) int   g_fill[NN];
__device__ __align__(128) int   g_rowptr[NN + 1];
__device__ __align__(128) int   g_flag[NBLK];
__device__ __align__(128) int   g_aggval[NBLK];
__device__ __align__(128) int   g_incval[NBLK];
__device__ __align__(128) unsigned g_cw4[EE + 32];  // packed (uint16 col | half w), padded
__device__ __align__(128) float g_h[NN * HH];       // fp32 master h
__device__ __align__(128) __half g_hh[NN * HH];     // fp16 mirror of h
__device__ __align__(128) __half g_tx[4][NN * HH];  // t1..t4 fp16
__device__ __align__(128) __half g_Ah[NN * HH];     // edge-pred A (fp16)
__device__ __align__(128) __half g_Bh[NN * HH];     // edge-pred B (fp16)
__device__ __align__(128) float g_pcol[NSLOT][HH];  // stats partials (coeff zeroes)
__device__ __align__(128) float g_psq[NSLOT];
__device__ float g_coeffs[PP + 1];

// packed dual-fp32 FMA (sm_103a)
__device__ __forceinline__ unsigned long long ffma2(unsigned long long a,
                                                    unsigned long long b,
                                                    unsigned long long c) {
    unsigned long long d;
    asm("fma.rn.f32x2 %0, %1, %2, %3;" : "=l"(d) : "l"(a), "l"(b), "l"(c));
    return d;
}
__device__ __forceinline__ unsigned long long pack2(float x, float y) {
    float2 t = make_float2(x, y);
    return *(unsigned long long*)&t;
}

// ---------------- graph build ----------------
__global__ void zero_build_kernel() {
    int i = blockIdx.x * blockDim.x + threadIdx.x;
    if (i < NN) { g_deg[i] = 0.f; g_cnt[i] = 0; g_fill[i] = 0; }
    if (i < NBLK) g_flag[i] = 0;
}

__global__ void deghist_kernel(const int* __restrict__ ei, const float* __restrict__ ew) {
    int e = blockIdx.x * blockDim.x + threadIdx.x;
    if (e >= EE) return;
    atomicAdd(&g_deg[ei[EE + e]], ew[e]);
    atomicAdd(&g_cnt[ei[e]], 1);
}

// single-pass scan (decoupled lookback) + dis fused
__global__ void scan_kernel() {
    __shared__ int s[SCAN_BLK];
    __shared__ int exc_s;
    int tid = threadIdx.x, b = blockIdx.x;
    int i = b * SCAN_BLK + tid;
    if (i < NN) {
        float v = rsqrtf(g_deg[i]);
        g_dis[i] = fminf(v, 1e6f);
    }
    int v = (i < NN) ? g_cnt[i] : 0;
    s[tid] = v;
    __syncthreads();
    for (int o = 1; o < SCAN_BLK; o <<= 1) {
        int t = (tid >= o) ? s[tid - o] : 0;
        __syncthreads();
        s[tid] += t;
        __syncthreads();
    }
    int agg = s[SCAN_BLK - 1];
    if (tid == 0) {
        if (b == 0) {
            g_incval[0] = agg;
            __threadfence();
            g_flag[0] = 2;
            exc_s = 0;
        } else {
            g_aggval[b] = agg;
            __threadfence();
            g_flag[b] = 1;
            int run = 0;
            for (int j = b - 1; ; --j) {
                int f;
                do { f = *(volatile int*)&g_flag[j]; } while (f == 0);
                __threadfence();
                if (f == 2) { run += *(volatile int*)&g_incval[j]; break; }
                run += *(volatile int*)&g_aggval[j];
            }
            exc_s = run;
            g_incval[b] = run + agg;
            __threadfence();
            g_flag[b] = 2;
        }
    }
    __syncthreads();
    int exc = exc_s;
    if (i < NN) g_rowptr[i] = exc + s[tid] - v;
    if (b == NBLK - 1 && tid == SCAN_BLK - 1) g_rowptr[NN] = exc + agg;
}

__global__ void scatter_kernel(const int* __restrict__ ei, const float* __restrict__ ew) {
    int e = blockIdx.x * blockDim.x + threadIdx.x;
    if (e >= EE) return;
    int r = ei[e], c = ei[EE + e];
    int pos = g_rowptr[r] + atomicAdd(&g_fill[r], 1);
    float w = g_dis[r] * ew[e] * g_dis[c];
    unsigned pk = (unsigned)c |
                  ((unsigned)__half_as_ushort(__float2half_rn(w)) << 16);
    g_cw4[pos] = pk;
}

// ---------------- input projection + layer-0 stats ----------------
__global__ void __launch_bounds__(256)
inproj_kernel(const float* __restrict__ x,
              const float* __restrict__ W,
              const float* __restrict__ b) {
    __shared__ float scol[HH];
    __shared__ float ssqs;
    int tid = threadIdx.x;
    if (tid < HH) scol[tid] = 0.f;
    if (tid == 0) ssqs = 0.f;
    __syncthreads();
    int g = blockIdx.x * 256 + tid;
    float s = 0.f;
    bool ok = g < NN * HH;
    if (ok) {
        int n = g >> 6, f = g & 63;
        s = b[f];
#pragma unroll
        for (int i = 0; i < FIN; ++i) s += x[n * FIN + i] * W[f * FIN + i];
        g_h[g] = s;
        g_hh[g] = __float2half(s);
        atomicAdd(&scol[g & 63], s);
    }
    float q = ok ? s * s : 0.f;
#pragma unroll
    for (int d = 16; d; d >>= 1) q += __shfl_xor_sync(0xffffffffu, q, d);
    if ((tid & 31) == 0) atomicAdd(&ssqs, q);
    __syncthreads();
    int slot = blockIdx.x & (NSLOT - 1);
    if (tid < HH) atomicAdd(&g_pcol[slot][tid], scol[tid]);
    if (tid == 64) atomicAdd(&g_psq[slot], ssqs);
}

// ---------------- coeff MLP (consumes + rezeros stats slots) ----------------
__global__ void coeff_kernel(const float* __restrict__ cW1, const float* __restrict__ cb1,
                             const float* __restrict__ cW2, const float* __restrict__ cb2) {
    __shared__ float colsum[HH];
    __shared__ float ci[CI];
    __shared__ float hid[32];
    __shared__ float logit[PP + 1];
    __shared__ float sq_s;
    int t = threadIdx.x;
    if (t < HH) {
        float s = 0.f;
        for (int b = 0; b < NSLOT; ++b) { s += g_pcol[b][t]; g_pcol[b][t] = 0.f; }
        colsum[t] = s;
        ci[t] = s / (float)NN;
    } else if (t >= 64 && t < 96) {
        int l = t - 64;
        float s = 0.f;
        for (int b = l; b < NSLOT; b += 32) { s += g_psq[b]; g_psq[b] = 0.f; }
#pragma unroll
        for (int d = 16; d; d >>= 1) s += __shfl_xor_sync(0xffffffffu, s, d);
        if (l == 0) sq_s = s;
    }
    __syncthreads();
    if (t == 0) {
        float tot = 0.f;
        for (int i = 0; i < HH; ++i) tot += colsum[i];
        const float M = (float)NN * (float)HH;
        float mean = tot / M;
        float var  = (sq_s - tot * tot / M) / (M - 1.0f);
        ci[64] = mean;
        ci[65] = sqrtf(fmaxf(var, 0.f));
        ci[66] = (float)NN;
        ci[67] = (float)EE;
    }
    __syncthreads();
    if (t < 32) {
        float s = cb1[t];
        for (int i = 0; i < CI; ++i) s += cW1[t * CI + i] * ci[i];
        hid[t] = fmaxf(s, 0.f);
    }
    __syncthreads();
    if (t < PP + 1) {
        float s = cb2[t];
        for (int i = 0; i < 32; ++i) s += cW2[t * 32 + i] * hid[i];
        logit[t] = s;
    }
    __syncthreads();
    if (t == 0) {
        float mx = logit[0];
        for (int i = 1; i <= PP; ++i) mx = fmaxf(mx, logit[i]);
        float den = 0.f, ex[PP + 1];
        for (int i = 0; i <= PP; ++i) { ex[i] = expf(logit[i] - mx); den += ex[i]; }
        for (int i = 0; i <= PP; ++i) g_coeffs[i] = ex[i] / den;
    }
}

// ---------------- SpMM v8: block 128, cw software-prefetch, 8/iter x unroll 2 --------
// FUSE=1 (k==PP): residual + LayerNorm + next-layer stats, res built from t1..t4.
template <int FUSE>
__global__ void __launch_bounds__(128)
spmm_kernel(int k,
            const float* __restrict__ lnsc,
            const float* __restrict__ lnbi,
            float* outh, int do_stats) {
    __shared__ float scol[HH];
    __shared__ float ssqs;
    int tid = threadIdx.x;
    if (FUSE) {
        if (tid < HH) scol[tid] = 0.f;
        if (tid == 0) ssqs = 0.f;
        __syncthreads();
    }
    int row = blockIdx.x * 4 + (tid >> 5);   // 12500 blocks x 4 warps
    int lane = tid & 31;
    int sub = lane >> 3, fl = lane & 7;

    const __half* tin = (k == 1) ? g_hh : g_tx[k - 2];

    int s = g_rowptr[row], e = g_rowptr[row + 1];
    unsigned long long a0 = 0ull, a1 = 0ull, a2 = 0ull, a3 = 0ull;

    // software prefetch of cw (g_cw4 is padded, unconditional loads safe)
    unsigned cwA = __ldg(&g_cw4[s + sub]);
    unsigned cwB = __ldg(&g_cw4[s + 4 + sub]);
#pragma unroll 2
    for (int jb = s; jb < e; jb += 8) {
        int jA = jb + sub, jB = jb + 4 + sub;
        int colA = (jA < e) ? (int)(cwA & 0xFFFFu) : 0;
        float wA  = (jA < e) ? __half2float(__ushort_as_half((unsigned short)(cwA >> 16))) : 0.f;
        int colB = (jB < e) ? (int)(cwB & 0xFFFFu) : 0;
        float wB  = (jB < e) ? __half2float(__ushort_as_half((unsigned short)(cwB >> 16))) : 0.f;
        uint4 dA = __ldg((const uint4*)tin + colA * 8 + fl);
        uint4 dB = __ldg((const uint4*)tin + colB * 8 + fl);
        cwA = __ldg(&g_cw4[jb + 8 + sub]);       // prefetch next iter
        cwB = __ldg(&g_cw4[jb + 12 + sub]);
        unsigned long long wpA = pack2(wA, wA);
        unsigned long long wpB = pack2(wB, wB);
        const __half2* hpA = (const __half2*)&dA;
        const __half2* hpB = (const __half2*)&dB;
        float2 vA0 = __half22float2(hpA[0]), vA1 = __half22float2(hpA[1]);
        float2 vA2 = __half22float2(hpA[2]), vA3 = __half22float2(hpA[3]);
        float2 vB0 = __half22float2(hpB[0]), vB1 = __half22float2(hpB[1]);
        float2 vB2 = __half22float2(hpB[2]), vB3 = __half22float2(hpB[3]);
        a0 = ffma2(wpA, *(unsigned long long*)&vA0, a0);
        a1 = ffma2(wpA, *(unsigned long long*)&vA1, a1);
        a2 = ffma2(wpA, *(unsigned long long*)&vA2, a2);
        a3 = ffma2(wpA, *(unsigned long long*)&vA3, a3);
        a0 = ffma2(wpB, *(unsigned long long*)&vB0, a0);
        a1 = ffma2(wpB, *(unsigned long long*)&vB1, a1);
        a2 = ffma2(wpB, *(unsigned long long*)&vB2, a2);
        a3 = ffma2(wpB, *(unsigned long long*)&vB3, a3);
    }

    float t[8];
    { float2 f0 = *(float2*)&a0, f1 = *(float2*)&a1, f2 = *(float2*)&a2, f3 = *(float2*)&a3;
      t[0]=f0.x; t[1]=f0.y; t[2]=f1.x; t[3]=f1.y; t[4]=f2.x; t[5]=f2.y; t[6]=f3.x; t[7]=f3.y; }
#pragma unroll
    for (int i = 0; i < 8; ++i) {
        t[i] += __shfl_xor_sync(0xffffffffu, t[i], 8);
        t[i] += __shfl_xor_sync(0xffffffffu, t[i], 16);
    }

    if (!FUSE) {
        if (sub == 0) {
            __half2 o0 = __floats2half2_rn(t[0], t[1]);
            __half2 o1 = __floats2half2_rn(t[2], t[3]);
            __half2 o2 = __floats2half2_rn(t[4], t[5]);
            __half2 o3 = __floats2half2_rn(t[6], t[7]);
            ((uint4*)g_tx[k - 1])[row * 8 + fl] =
                make_uint4(*(unsigned*)&o0, *(unsigned*)&o1, *(unsigned*)&o2, *(unsigned*)&o3);
        }
    } else {
        float c0 = g_coeffs[0], c1 = g_coeffs[1], c2 = g_coeffs[2];
        float c3 = g_coeffs[3], c4 = g_coeffs[4], c5 = g_coeffs[5];
        float4 h0 = __ldg((const float4*)g_h + row * 16 + fl * 2);
        float4 h1 = __ldg((const float4*)g_h + row * 16 + fl * 2 + 1);
        uint4 x1 = __ldg((const uint4*)g_tx[0] + row * 8 + fl);
        uint4 x2 = __ldg((const uint4*)g_tx[1] + row * 8 + fl);
        uint4 x3 = __ldg((const uint4*)g_tx[2] + row * 8 + fl);
        uint4 x4 = __ldg((const uint4*)g_tx[3] + row * 8 + fl);
        const __half2 *p1 = (const __half2*)&x1, *p2 = (const __half2*)&x2;
        const __half2 *p3 = (const __half2*)&x3, *p4 = (const __half2*)&x4;
        float hv[8], v[8];
        hv[0]=h0.x; hv[1]=h0.y; hv[2]=h0.z; hv[3]=h0.w;
        hv[4]=h1.x; hv[5]=h1.y; hv[6]=h1.z; hv[7]=h1.w;
#pragma unroll
        for (int i = 0; i < 4; ++i) {
            float2 t1v = __half22float2(p1[i]);
            float2 t2v = __half22float2(p2[i]);
            float2 t3v = __half22float2(p3[i]);
            float2 t4v = __half22float2(p4[i]);
            float rx = c0*hv[2*i] + c1*t1v.x + c2*t2v.x + c3*t3v.x + c4*t4v.x + c5*t[2*i];
            float ry = c0*hv[2*i+1] + c1*t1v.y + c2*t2v.y + c3*t3v.y + c4*t4v.y + c5*t[2*i+1];
            v[2*i]   = hv[2*i] + rx;
            v[2*i+1] = hv[2*i+1] + ry;
        }
        float ps = 0.f;
#pragma unroll
        for (int i = 0; i < 8; ++i) ps += v[i];
#pragma unroll
        for (int d = 1; d <= 4; d <<= 1) ps += __shfl_xor_sync(0xffffffffu, ps, d);
        float m = ps * (1.0f / HH);
        float q = 0.f;
#pragma unroll
        for (int i = 0; i < 8; ++i) { v[i] -= m; q += v[i] * v[i]; }
#pragma unroll
        for (int d = 1; d <= 4; d <<= 1) q += __shfl_xor_sync(0xffffffffu, q, d);
        float inv = rsqrtf(q * (1.0f / HH) + 1e-5f);
        float4 s0 = __ldg((const float4*)lnsc + fl * 2);
        float4 s1 = __ldg((const float4*)lnsc + fl * 2 + 1);
        float4 b0 = __ldg((const float4*)lnbi + fl * 2);
        float4 b1 = __ldg((const float4*)lnbi + fl * 2 + 1);
        float o[8];
        o[0]=v[0]*inv*s0.x+b0.x; o[1]=v[1]*inv*s0.y+b0.y;
        o[2]=v[2]*inv*s0.z+b0.z; o[3]=v[3]*inv*s0.w+b0.w;
        o[4]=v[4]*inv*s1.x+b1.x; o[5]=v[5]*inv*s1.y+b1.y;
        o[6]=v[6]*inv*s1.z+b1.z; o[7]=v[7]*inv*s1.w+b1.w;
        if (sub == 0) {
            float4 w0 = make_float4(o[0],o[1],o[2],o[3]);
            float4 w1 = make_float4(o[4],o[5],o[6],o[7]);
            ((float4*)g_h)[row * 16 + fl * 2]     = w0;
            ((float4*)g_h)[row * 16 + fl * 2 + 1] = w1;
            __half2 q0 = __floats2half2_rn(o[0],o[1]);
            __half2 q1 = __floats2half2_rn(o[2],o[3]);
            __half2 q2 = __floats2half2_rn(o[4],o[5]);
            __half2 q3 = __floats2half2_rn(o[6],o[7]);
            ((uint4*)g_hh)[row * 8 + fl] = make_uint4(*(unsigned*)&q0, *(unsigned*)&q1,
                                                      *(unsigned*)&q2, *(unsigned*)&q3);
            if (outh) {
                ((float4*)outh)[row * 16 + fl * 2]     = w0;
                ((float4*)outh)[row * 16 + fl * 2 + 1] = w1;
            }
        }
        if (do_stats) {
            if (sub == 0) {
#pragma unroll
                for (int i = 0; i < 8; ++i) atomicAdd(&scol[fl * 8 + i], o[i]);
            }
            float so = 0.f;
#pragma unroll
            for (int i = 0; i < 8; ++i) so += o[i] * o[i];
#pragma unroll
            for (int d = 1; d <= 4; d <<= 1) so += __shfl_xor_sync(0xffffffffu, so, d);
            if (lane == 0) atomicAdd(&ssqs, so);
            __syncthreads();
            int slot = blockIdx.x & (NSLOT - 1);
            if (tid < HH) atomicAdd(&g_pcol[slot][tid], scol[tid]);
            if (tid == 64) atomicAdd(&g_psq[slot], ssqs);
        }
    }
}

// ---------------- edge predictor A/B: 16 nodes per 256-thr block ----------------
__global__ void __launch_bounds__(256)
abgemm_kernel(const float* __restrict__ epW1) {
    __shared__ float WtA[64 * 64];
    __shared__ float WtB[64 * 64];
    __shared__ float hs[16 * 64];
    int tid = threadIdx.x;
    for (int idx = tid; idx < 4096; idx += 256) {
        int f = idx >> 6, i = idx & 63;
        WtA[i * 64 + f] = epW1[f * 128 + i];
        WtB[i * 64 + f] = epW1[f * 128 + 64 + i];
    }
    int n0 = blockIdx.x * 16;
    for (int idx = tid; idx < 16 * 64; idx += 256)
        hs[idx] = g_h[n0 * 64 + idx];
    __syncthreads();
#pragma unroll
    for (int rep = 0; rep < 4; ++rep) {
        int oidx = rep * 256 + tid;
        int ln = oidx >> 6, f = oidx & 63;
        float a = 0.f, b = 0.f;
#pragma unroll
        for (int i = 0; i < 64; ++i) {
            float hv = hs[ln * 64 + i];
            a += hv * WtA[i * 64 + f];
            b += hv * WtB[i * 64 + f];
        }
        g_Ah[(n0 + ln) * 64 + f] = __float2half(a);
        g_Bh[(n0 + ln) * 64 + f] = __float2half(b);
    }
}

// ---------------- edge kernel: coop gather -> wmma second layer ----------------
#define E1LD 72   // padded half stride
#define E2LD 36   // padded float stride
__global__ void __launch_bounds__(128)
edge_kernel(const int* __restrict__ ei,
            const float* __restrict__ epb1,
            const float* __restrict__ epW2, const float* __restrict__ epb2,
            const float* __restrict__ epW3, const float* __restrict__ epb3,
            float* __restrict__ out) {
    __shared__ __half e1s[128 * E1LD];
    __shared__ __half W2h[32 * 64];
    __shared__ float  e2s[128 * E2LD];
    __shared__ float  b2s[32], W3s[32];
    __shared__ float  b3s;
    int tid = threadIdx.x;
    int w = tid >> 5, lane = tid & 31, sub = lane >> 3, fl = lane & 7;
    for (int idx = tid; idx < 2048; idx += 128) W2h[idx] = __float2half(epW2[idx]);
    if (tid < 32) { b2s[tid] = epb2[tid]; W3s[tid] = epW3[tid]; }
    if (tid == 0) b3s = epb3[0];
    __syncthreads();

    int base = blockIdx.x * 128 + w * 32;
    int r_own = ei[base + lane];
    int c_own = ei[EE + base + lane];
    float4 bb0 = __ldg((const float4*)epb1 + fl * 2);
    float4 bb1 = __ldg((const float4*)epb1 + fl * 2 + 1);
    float2 bias[4] = { make_float2(bb0.x, bb0.y), make_float2(bb0.z, bb0.w),
                       make_float2(bb1.x, bb1.y), make_float2(bb1.z, bb1.w) };
#pragma unroll
    for (int step = 0; step < 8; ++step) {
        int idx = step * 4 + sub;
        int rj = __shfl_sync(0xffffffffu, r_own, idx);
        int cj = __shfl_sync(0xffffffffu, c_own, idx);
        uint4 a4 = __ldg((const uint4*)g_Ah + rj * 8 + fl);
        uint4 b4 = __ldg((const uint4*)g_Bh + cj * 8 + fl);
        const __half2* ap = (const __half2*)&a4;
        const __half2* bp = (const __half2*)&b4;
        int e_local = w * 32 + idx;
#pragma unroll
        for (int kk = 0; kk < 4; ++kk) {
            float2 av = __half22float2(ap[kk]);
            float2 bv = __half22float2(bp[kk]);
            float vx = fmaxf(av.x + bv.x + bias[kk].x, 0.f);
            float vy = fmaxf(av.y + bv.y + bias[kk].y, 0.f);
            *(__half2*)(e1s + e_local * E1LD + (fl * 4 + kk) * 2) = __floats2half2_rn(vx, vy);
        }
    }
    __syncwarp();

    wmma::fragment<wmma::matrix_b, 16, 16, 16, __half, wmma::col_major> bf[4][2];
#pragma unroll
    for (int kk = 0; kk < 4; ++kk)
#pragma unroll
        for (int n = 0; n < 2; ++n)
            wmma::load_matrix_sync(bf[kk][n], W2h + n * 16 * 64 + kk * 16, 64);
#pragma unroll
    for (int m = 0; m < 2; ++m) {
        wmma::fragment<wmma::accumulator, 16, 16, 16, float> cf[2];
        wmma::fill_fragment(cf[0], 0.f);
        wmma::fill_fragment(cf[1], 0.f);
#pragma unroll
        for (int kk = 0; kk < 4; ++kk) {
            wmma::fragment<wmma::matrix_a, 16, 16, 16, __half, wmma::row_major> af;
            wmma::load_matrix_sync(af, e1s + (w * 32 + m * 16) * E1LD + kk * 16, E1LD);
            wmma::mma_sync(cf[0], af, bf[kk][0], cf[0]);
            wmma::mma_sync(cf[1], af, bf[kk][1], cf[1]);
        }
        wmma::store_matrix_sync(e2s + (w * 32 + m * 16) * E2LD, cf[0], E2LD, wmma::mem_row_major);
        wmma::store_matrix_sync(e2s + (w * 32 + m * 16) * E2LD + 16, cf[1], E2LD, wmma::mem_row_major);
    }
    __syncwarp();

    const float* rowp = e2s + tid * E2LD;
    float acc = b3s;
#pragma unroll
    for (int o = 0; o < 32; ++o)
        acc += W3s[o] * fmaxf(rowp[o] + b2s[o], 0.f);
    out[blockIdx.x * 128 + tid] = 1.0f / (1.0f + expf(-acc));
}

// ---------------- launch ----------------
extern "C" void kernel_launch(void* const* d_in, const int* in_sizes, int n_in,
                              void* d_out, int out_size) {
    const float* x    = (const float*)d_in[0];
    const int*   ei   = (const int*)d_in[1];
    const float* ew   = (const float*)d_in[2];
    const float* W_in = (const float*)d_in[3];
    const float* b_in = (const float*)d_in[4];
    const float* cW1  = (const float*)d_in[5];
    const float* cb1  = (const float*)d_in[6];
    const float* cW2  = (const float*)d_in[7];
    const float* cb2  = (const float*)d_in[8];
    const float* lns  = (const float*)d_in[9];
    const float* lnb  = (const float*)d_in[10];
    const float* epW1 = (const float*)d_in[11];
    const float* epb1 = (const float*)d_in[12];
    const float* epW2 = (const float*)d_in[13];
    const float* epb2 = (const float*)d_in[14];
    const float* epW3 = (const float*)d_in[15];
    const float* epb3 = (const float*)d_in[16];
    float* out = (float*)d_out;

    const int NB = (NN + 255) / 256;
    const int EB = (EE + 255) / 256;
    const int SB = NN / 4;   // spmm blocks (128 thr, 4 rows): 12500

    zero_build_kernel<<<NB, 256>>>();
    deghist_kernel<<<EB, 256>>>(ei, ew);
    scan_kernel<<<NBLK, SCAN_BLK>>>();
    scatter_kernel<<<EB, 256>>>(ei, ew);
    inproj_kernel<<<(NN * HH) / 256, 256>>>(x, W_in, b_in);

    for (int l = 0; l < LL; ++l) {
        coeff_kernel<<<1, 128>>>(cW1 + l * 32 * CI, cb1 + l * 32,
                                 cW2 + l * (PP + 1) * 32, cb2 + l * (PP + 1));
        for (int k = 1; k < PP; ++k)
            spmm_kernel<0><<<SB, 128>>>(k, (const float*)nullptr, (const float*)nullptr,
                                        (float*)nullptr, 0);
        spmm_kernel<1><<<SB, 128>>>(PP, lns + l * HH, lnb + l * HH,
                                    (l == LL - 1) ? (out + EE) : (float*)nullptr,
                                    (l < LL - 1) ? 1 : 0);
    }

    abgemm_kernel<<<NN / 16, 256>>>(epW1);
    edge_kernel<<<EE / 128, 128>>>(ei, epb1, epW2, epb2, epW3, epb3, out);
}

// round 13
// speedup vs baseline: 1.4815x; 1.4815x over previous
#include <cuda_runtime.h>
#include <cuda_fp16.h>
#include <mma.h>
#include <math.h>

using namespace nvcuda;

#define NN 50000
#define EE 1600000
#define HH 64
#define FIN 8
#define PP 5
#define LL 3
#define CI 68   // H + 4
#define SCAN_BLK 256
#define NBLK ((NN + SCAN_BLK - 1) / SCAN_BLK)   // 196
#define NSLOT 64

// ---------------- scratch (device globals; no allocation) ----------------
__device__ __align__(128) float g_deg[NN];
__device__ __align__(128) float g_dis[NN];
__device__ __align__(128) int   g_cnt[NN];
__device__ __align__(128) int   g_fill[NN];
__device__ __align__(128) int   g_rowptr[NN + 1];
__device__ __align__(128) int   g_flag[NBLK];
__device__ __align__(128) int   g_aggval[NBLK];
__device__ __align__(128) int   g_incval[NBLK];
__device__ __align__(128) unsigned g_cw4[EE + 16];  // packed (uint16 col | half w)
__device__ __align__(128) float g_h[NN * HH];       // fp32 master h
__device__ __align__(128) __half g_hh[NN * HH];     // fp16 mirror of h
__device__ __align__(128) __half g_tx[4][NN * HH];  // t1..t4 fp16
__device__ __align__(128) __half g_Ah[NN * HH];     // edge-pred A (fp16)
__device__ __align__(128) __half g_Bh[NN * HH];     // edge-pred B (fp16)
__device__ __align__(128) float g_pcol[NSLOT][HH];  // stats partials (coeff zeroes)
__device__ __align__(128) float g_psq[NSLOT];
__device__ float g_coeffs[PP + 1];

// packed dual-fp32 FMA (sm_103a)
__device__ __forceinline__ unsigned long long ffma2(unsigned long long a,
                                                    unsigned long long b,
                                                    unsigned long long c) {
    unsigned long long d;
    asm("fma.rn.f32x2 %0, %1, %2, %3;" : "=l"(d) : "l"(a), "l"(b), "l"(c));
    return d;
}
__device__ __forceinline__ unsigned long long pack2(float x, float y) {
    float2 t = make_float2(x, y);
    return *(unsigned long long*)&t;
}

// ---------------- graph build ----------------
__global__ void zero_build_kernel() {
    int i = blockIdx.x * blockDim.x + threadIdx.x;
    if (i < NN) { g_deg[i] = 0.f; g_cnt[i] = 0; g_fill[i] = 0; }
    if (i < NBLK) g_flag[i] = 0;
}

__global__ void deghist_kernel(const int* __restrict__ ei, const float* __restrict__ ew) {
    int e = blockIdx.x * blockDim.x + threadIdx.x;
    if (e >= EE) return;
    atomicAdd(&g_deg[ei[EE + e]], ew[e]);
    atomicAdd(&g_cnt[ei[e]], 1);
}

// single-pass scan (decoupled lookback) + dis fused
__global__ void scan_kernel() {
    __shared__ int s[SCAN_BLK];
    __shared__ int exc_s;
    int tid = threadIdx.x, b = blockIdx.x;
    int i = b * SCAN_BLK + tid;
    if (i < NN) {
        float v = rsqrtf(g_deg[i]);
        g_dis[i] = fminf(v, 1e6f);
    }
    int v = (i < NN) ? g_cnt[i] : 0;
    s[tid] = v;
    __syncthreads();
    for (int o = 1; o < SCAN_BLK; o <<= 1) {
        int t = (tid >= o) ? s[tid - o] : 0;
        __syncthreads();
        s[tid] += t;
        __syncthreads();
    }
    int agg = s[SCAN_BLK - 1];
    if (tid == 0) {
        if (b == 0) {
            g_incval[0] = agg;
            __threadfence();
            g_flag[0] = 2;
            exc_s = 0;
        } else {
            g_aggval[b] = agg;
            __threadfence();
            g_flag[b] = 1;
            int run = 0;
            for (int j = b - 1; ; --j) {
                int f;
                do { f = *(volatile int*)&g_flag[j]; } while (f == 0);
                __threadfence();
                if (f == 2) { run += *(volatile int*)&g_incval[j]; break; }
                run += *(volatile int*)&g_aggval[j];
            }
            exc_s = run;
            g_incval[b] = run + agg;
            __threadfence();
            g_flag[b] = 2;
        }
    }
    __syncthreads();
    int exc = exc_s;
    if (i < NN) g_rowptr[i] = exc + s[tid] - v;
    if (b == NBLK - 1 && tid == SCAN_BLK - 1) g_rowptr[NN] = exc + agg;
}

__global__ void scatter_kernel(const int* __restrict__ ei, const float* __restrict__ ew) {
    int e = blockIdx.x * blockDim.x + threadIdx.x;
    if (e >= EE) return;
    int r = ei[e], c = ei[EE + e];
    int pos = g_rowptr[r] + atomicAdd(&g_fill[r], 1);
    float w = g_dis[r] * ew[e] * g_dis[c];
    unsigned pk = (unsigned)c |
                  ((unsigned)__half_as_ushort(__float2half_rn(w)) << 16);
    g_cw4[pos] = pk;
}

// ---------------- input projection + layer-0 stats ----------------
__global__ void __launch_bounds__(256)
inproj_kernel(const float* __restrict__ x,
              const float* __restrict__ W,
              const float* __restrict__ b) {
    __shared__ float scol[HH];
    __shared__ float ssqs;
    int tid = threadIdx.x;
    if (tid < HH) scol[tid] = 0.f;
    if (tid == 0) ssqs = 0.f;
    __syncthreads();
    int g = blockIdx.x * 256 + tid;
    float s = 0.f;
    bool ok = g < NN * HH;
    if (ok) {
        int n = g >> 6, f = g & 63;
        s = b[f];
#pragma unroll
        for (int i = 0; i < FIN; ++i) s += x[n * FIN + i] * W[f * FIN + i];
        g_h[g] = s;
        g_hh[g] = __float2half(s);
        atomicAdd(&scol[g & 63], s);
    }
    float q = ok ? s * s : 0.f;
#pragma unroll
    for (int d = 16; d; d >>= 1) q += __shfl_xor_sync(0xffffffffu, q, d);
    if ((tid & 31) == 0) atomicAdd(&ssqs, q);
    __syncthreads();
    int slot = blockIdx.x & (NSLOT - 1);
    if (tid < HH) atomicAdd(&g_pcol[slot][tid], scol[tid]);
    if (tid == 64) atomicAdd(&g_psq[slot], ssqs);
}

// ---------------- coeff MLP (consumes + rezeros stats slots) ----------------
__global__ void coeff_kernel(const float* __restrict__ cW1, const float* __restrict__ cb1,
                             const float* __restrict__ cW2, const float* __restrict__ cb2) {
    __shared__ float colsum[HH];
    __shared__ float ci[CI];
    __shared__ float hid[32];
    __shared__ float logit[PP + 1];
    __shared__ float sq_s;
    int t = threadIdx.x;
    if (t < HH) {
        float s = 0.f;
        for (int b = 0; b < NSLOT; ++b) { s += g_pcol[b][t]; g_pcol[b][t] = 0.f; }
        colsum[t] = s;
        ci[t] = s / (float)NN;
    } else if (t >= 64 && t < 96) {
        int l = t - 64;
        float s = 0.f;
        for (int b = l; b < NSLOT; b += 32) { s += g_psq[b]; g_psq[b] = 0.f; }
#pragma unroll
        for (int d = 16; d; d >>= 1) s += __shfl_xor_sync(0xffffffffu, s, d);
        if (l == 0) sq_s = s;
    }
    __syncthreads();
    if (t == 0) {
        float tot = 0.f;
        for (int i = 0; i < HH; ++i) tot += colsum[i];
        const float M = (float)NN * (float)HH;
        float mean = tot / M;
        float var  = (sq_s - tot * tot / M) / (M - 1.0f);
        ci[64] = mean;
        ci[65] = sqrtf(fmaxf(var, 0.f));
        ci[66] = (float)NN;
        ci[67] = (float)EE;
    }
    __syncthreads();
    if (t < 32) {
        float s = cb1[t];
        for (int i = 0; i < CI; ++i) s += cW1[t * CI + i] * ci[i];
        hid[t] = fmaxf(s, 0.f);
    }
    __syncthreads();
    if (t < PP + 1) {
        float s = cb2[t];
        for (int i = 0; i < 32; ++i) s += cW2[t * 32 + i] * hid[i];
        logit[t] = s;
    }
    __syncthreads();
    if (t == 0) {
        float mx = logit[0];
        for (int i = 1; i <= PP; ++i) mx = fmaxf(mx, logit[i]);
        float den = 0.f, ex[PP + 1];
        for (int i = 0; i <= PP; ++i) { ex[i] = expf(logit[i] - mx); den += ex[i]; }
        for (int i = 0; i <= PP; ++i) g_coeffs[i] = ex[i] / den;
    }
}

// ---------------- SpMM (R8 known-good): 256-thr blocks, 8/iter, unroll 2 ----------
// FUSE=1 (k==PP): residual + LayerNorm + next-layer stats, res built from t1..t4.
template <int FUSE>
__global__ void __launch_bounds__(256)
spmm_kernel(int k,
            const float* __restrict__ lnsc,
            const float* __restrict__ lnbi,
            float* outh, int do_stats) {
    __shared__ float scol[HH];
    __shared__ float ssqs;
    int tid = threadIdx.x;
    if (FUSE) {
        if (tid < HH) scol[tid] = 0.f;
        if (tid == 0) ssqs = 0.f;
        __syncthreads();
    }
    int row = (blockIdx.x * blockDim.x + tid) >> 5;   // grid exact: 50000 warps
    int lane = tid & 31;
    int sub = lane >> 3, fl = lane & 7;

    const __half* tin = (k == 1) ? g_hh : g_tx[k - 2];

    int s = g_rowptr[row], e = g_rowptr[row + 1];
    unsigned long long a0 = 0ull, a1 = 0ull, a2 = 0ull, a3 = 0ull;

#pragma unroll 2
    for (int jb = s; jb < e; jb += 8) {
        int jA = jb + sub, jB = jb + 4 + sub;
        unsigned cwA = __ldg(&g_cw4[jA]);
        unsigned cwB = __ldg(&g_cw4[jB]);
        int colA = (jA < e) ? (int)(cwA & 0xFFFFu) : 0;
        float wA  = (jA < e) ? __half2float(__ushort_as_half((unsigned short)(cwA >> 16))) : 0.f;
        int colB = (jB < e) ? (int)(cwB & 0xFFFFu) : 0;
        float wB  = (jB < e) ? __half2float(__ushort_as_half((unsigned short)(cwB >> 16))) : 0.f;
        uint4 dA = __ldg((const uint4*)tin + colA * 8 + fl);
        uint4 dB = __ldg((const uint4*)tin + colB * 8 + fl);
        unsigned long long wpA = pack2(wA, wA);
        unsigned long long wpB = pack2(wB, wB);
        const __half2* hpA = (const __half2*)&dA;
        const __half2* hpB = (const __half2*)&dB;
        float2 vA0 = __half22float2(hpA[0]), vA1 = __half22float2(hpA[1]);
        float2 vA2 = __half22float2(hpA[2]), vA3 = __half22float2(hpA[3]);
        float2 vB0 = __half22float2(hpB[0]), vB1 = __half22float2(hpB[1]);
        float2 vB2 = __half22float2(hpB[2]), vB3 = __half22float2(hpB[3]);
        a0 = ffma2(wpA, *(unsigned long long*)&vA0, a0);
        a1 = ffma2(wpA, *(unsigned long long*)&vA1, a1);
        a2 = ffma2(wpA, *(unsigned long long*)&vA2, a2);
        a3 = ffma2(wpA, *(unsigned long long*)&vA3, a3);
        a0 = ffma2(wpB, *(unsigned long long*)&vB0, a0);
        a1 = ffma2(wpB, *(unsigned long long*)&vB1, a1);
        a2 = ffma2(wpB, *(unsigned long long*)&vB2, a2);
        a3 = ffma2(wpB, *(unsigned long long*)&vB3, a3);
    }

    float t[8];
    { float2 f0 = *(float2*)&a0, f1 = *(float2*)&a1, f2 = *(float2*)&a2, f3 = *(float2*)&a3;
      t[0]=f0.x; t[1]=f0.y; t[2]=f1.x; t[3]=f1.y; t[4]=f2.x; t[5]=f2.y; t[6]=f3.x; t[7]=f3.y; }
#pragma unroll
    for (int i = 0; i < 8; ++i) {
        t[i] += __shfl_xor_sync(0xffffffffu, t[i], 8);
        t[i] += __shfl_xor_sync(0xffffffffu, t[i], 16);
    }

    if (!FUSE) {
        if (sub == 0) {
            __half2 o0 = __floats2half2_rn(t[0], t[1]);
            __half2 o1 = __floats2half2_rn(t[2], t[3]);
            __half2 o2 = __floats2half2_rn(t[4], t[5]);
            __half2 o3 = __floats2half2_rn(t[6], t[7]);
            ((uint4*)g_tx[k - 1])[row * 8 + fl] =
                make_uint4(*(unsigned*)&o0, *(unsigned*)&o1, *(unsigned*)&o2, *(unsigned*)&o3);
        }
    } else {
        float c0 = g_coeffs[0], c1 = g_coeffs[1], c2 = g_coeffs[2];
        float c3 = g_coeffs[3], c4 = g_coeffs[4], c5 = g_coeffs[5];
        float4 h0 = __ldg((const float4*)g_h + row * 16 + fl * 2);
        float4 h1 = __ldg((const float4*)g_h + row * 16 + fl * 2 + 1);
        uint4 x1 = __ldg((const uint4*)g_tx[0] + row * 8 + fl);
        uint4 x2 = __ldg((const uint4*)g_tx[1] + row * 8 + fl);
        uint4 x3 = __ldg((const uint4*)g_tx[2] + row * 8 + fl);
        uint4 x4 = __ldg((const uint4*)g_tx[3] + row * 8 + fl);
        const __half2 *p1 = (const __half2*)&x1, *p2 = (const __half2*)&x2;
        const __half2 *p3 = (const __half2*)&x3, *p4 = (const __half2*)&x4;
        float hv[8], v[8];
        hv[0]=h0.x; hv[1]=h0.y; hv[2]=h0.z; hv[3]=h0.w;
        hv[4]=h1.x; hv[5]=h1.y; hv[6]=h1.z; hv[7]=h1.w;
#pragma unroll
        for (int i = 0; i < 4; ++i) {
            float2 t1v = __half22float2(p1[i]);
            float2 t2v = __half22float2(p2[i]);
            float2 t3v = __half22float2(p3[i]);
            float2 t4v = __half22float2(p4[i]);
            float rx = c0*hv[2*i] + c1*t1v.x + c2*t2v.x + c3*t3v.x + c4*t4v.x + c5*t[2*i];
            float ry = c0*hv[2*i+1] + c1*t1v.y + c2*t2v.y + c3*t3v.y + c4*t4v.y + c5*t[2*i+1];
            v[2*i]   = hv[2*i] + rx;
            v[2*i+1] = hv[2*i+1] + ry;
        }
        float ps = 0.f;
#pragma unroll
        for (int i = 0; i < 8; ++i) ps += v[i];
#pragma unroll
        for (int d = 1; d <= 4; d <<= 1) ps += __shfl_xor_sync(0xffffffffu, ps, d);
        float m = ps * (1.0f / HH);
        float q = 0.f;
#pragma unroll
        for (int i = 0; i < 8; ++i) { v[i] -= m; q += v[i] * v[i]; }
#pragma unroll
        for (int d = 1; d <= 4; d <<= 1) q += __shfl_xor_sync(0xffffffffu, q, d);
        float inv = rsqrtf(q * (1.0f / HH) + 1e-5f);
        float4 s0 = __ldg((const float4*)lnsc + fl * 2);
        float4 s1 = __ldg((const float4*)lnsc + fl * 2 + 1);
        float4 b0 = __ldg((const float4*)lnbi + fl * 2);
        float4 b1 = __ldg((const float4*)lnbi + fl * 2 + 1);
        float o[8];
        o[0]=v[0]*inv*s0.x+b0.x; o[1]=v[1]*inv*s0.y+b0.y;
        o[2]=v[2]*inv*s0.z+b0.z; o[3]=v[3]*inv*s0.w+b0.w;
        o[4]=v[4]*inv*s1.x+b1.x; o[5]=v[5]*inv*s1.y+b1.y;
        o[6]=v[6]*inv*s1.z+b1.z; o[7]=v[7]*inv*s1.w+b1.w;
        if (sub == 0) {
            float4 w0 = make_float4(o[0],o[1],o[2],o[3]);
            float4 w1 = make_float4(o[4],o[5],o[6],o[7]);
            ((float4*)g_h)[row * 16 + fl * 2]     = w0;
            ((float4*)g_h)[row * 16 + fl * 2 + 1] = w1;
            __half2 q0 = __floats2half2_rn(o[0],o[1]);
            __half2 q1 = __floats2half2_rn(o[2],o[3]);
            __half2 q2 = __floats2half2_rn(o[4],o[5]);
            __half2 q3 = __floats2half2_rn(o[6],o[7]);
            ((uint4*)g_hh)[row * 8 + fl] = make_uint4(*(unsigned*)&q0, *(unsigned*)&q1,
                                                      *(unsigned*)&q2, *(unsigned*)&q3);
            if (outh) {
                ((float4*)outh)[row * 16 + fl * 2]     = w0;
                ((float4*)outh)[row * 16 + fl * 2 + 1] = w1;
            }
        }
        if (do_stats) {
            if (sub == 0) {
#pragma unroll
                for (int i = 0; i < 8; ++i) atomicAdd(&scol[fl * 8 + i], o[i]);
            }
            float so = 0.f;
#pragma unroll
            for (int i = 0; i < 8; ++i) so += o[i] * o[i];
#pragma unroll
            for (int d = 1; d <= 4; d <<= 1) so += __shfl_xor_sync(0xffffffffu, so, d);
            if (lane == 0) atomicAdd(&ssqs, so);
            __syncthreads();
            int slot = blockIdx.x & (NSLOT - 1);
            if (tid < HH) atomicAdd(&g_pcol[slot][tid], scol[tid]);
            if (tid == 64) atomicAdd(&g_psq[slot], ssqs);
        }
    }
}

// ---------------- edge predictor A/B: 16 nodes per 256-thr block ----------------
__global__ void __launch_bounds__(256)
abgemm_kernel(const float* __restrict__ epW1) {
    __shared__ float WtA[64 * 64];
    __shared__ float WtB[64 * 64];
    __shared__ float hs[16 * 64];
    int tid = threadIdx.x;
    for (int idx = tid; idx < 4096; idx += 256) {
        int f = idx >> 6, i = idx & 63;
        WtA[i * 64 + f] = epW1[f * 128 + i];
        WtB[i * 64 + f] = epW1[f * 128 + 64 + i];
    }
    int n0 = blockIdx.x * 16;
    for (int idx = tid; idx < 16 * 64; idx += 256)
        hs[idx] = g_h[n0 * 64 + idx];
    __syncthreads();
#pragma unroll
    for (int rep = 0; rep < 4; ++rep) {
        int oidx = rep * 256 + tid;
        int ln = oidx >> 6, f = oidx & 63;
        float a = 0.f, b = 0.f;
#pragma unroll
        for (int i = 0; i < 64; ++i) {
            float hv = hs[ln * 64 + i];
            a += hv * WtA[i * 64 + f];
            b += hv * WtB[i * 64 + f];
        }
        g_Ah[(n0 + ln) * 64 + f] = __float2half(a);
        g_Bh[(n0 + ln) * 64 + f] = __float2half(b);
    }
}

// ---------------- edge kernel: coop gather -> wmma second layer ----------------
#define E1LD 72   // padded half stride
#define E2LD 36   // padded float stride
__global__ void __launch_bounds__(128)
edge_kernel(const int* __restrict__ ei,
            const float* __restrict__ epb1,
            const float* __restrict__ epW2, const float* __restrict__ epb2,
            const float* __restrict__ epW3, const float* __restrict__ epb3,
            float* __restrict__ out) {
    __shared__ __half e1s[128 * E1LD];
    __shared__ __half W2h[32 * 64];
    __shared__ float  e2s[128 * E2LD];
    __shared__ float  b2s[32], W3s[32];
    __shared__ float  b3s;
    int tid = threadIdx.x;
    int w = tid >> 5, lane = tid & 31, sub = lane >> 3, fl = lane & 7;
    for (int idx = tid; idx < 2048; idx += 128) W2h[idx] = __float2half(epW2[idx]);
    if (tid < 32) { b2s[tid] = epb2[tid]; W3s[tid] = epW3[tid]; }
    if (tid == 0) b3s = epb3[0];
    __syncthreads();

    int base = blockIdx.x * 128 + w * 32;
    int r_own = ei[base + lane];
    int c_own = ei[EE + base + lane];
    float4 bb0 = __ldg((const float4*)epb1 + fl * 2);
    float4 bb1 = __ldg((const float4*)epb1 + fl * 2 + 1);
    float2 bias[4] = { make_float2(bb0.x, bb0.y), make_float2(bb0.z, bb0.w),
                       make_float2(bb1.x, bb1.y), make_float2(bb1.z, bb1.w) };
#pragma unroll
    for (int step = 0; step < 8; ++step) {
        int idx = step * 4 + sub;
        int rj = __shfl_sync(0xffffffffu, r_own, idx);
        int cj = __shfl_sync(0xffffffffu, c_own, idx);
        uint4 a4 = __ldg((const uint4*)g_Ah + rj * 8 + fl);
        uint4 b4 = __ldg((const uint4*)g_Bh + cj * 8 + fl);
        const __half2* ap = (const __half2*)&a4;
        const __half2* bp = (const __half2*)&b4;
        int e_local = w * 32 + idx;
#pragma unroll
        for (int kk = 0; kk < 4; ++kk) {
            float2 av = __half22float2(ap[kk]);
            float2 bv = __half22float2(bp[kk]);
            float vx = fmaxf(av.x + bv.x + bias[kk].x, 0.f);
            float vy = fmaxf(av.y + bv.y + bias[kk].y, 0.f);
            *(__half2*)(e1s + e_local * E1LD + (fl * 4 + kk) * 2) = __floats2half2_rn(vx, vy);
        }
    }
    __syncwarp();

    wmma::fragment<wmma::matrix_b, 16, 16, 16, __half, wmma::col_major> bf[4][2];
#pragma unroll
    for (int kk = 0; kk < 4; ++kk)
#pragma unroll
        for (int n = 0; n < 2; ++n)
            wmma::load_matrix_sync(bf[kk][n], W2h + n * 16 * 64 + kk * 16, 64);
#pragma unroll
    for (int m = 0; m < 2; ++m) {
        wmma::fragment<wmma::accumulator, 16, 16, 16, float> cf[2];
        wmma::fill_fragment(cf[0], 0.f);
        wmma::fill_fragment(cf[1], 0.f);
#pragma unroll
        for (int kk = 0; kk < 4; ++kk) {
            wmma::fragment<wmma::matrix_a, 16, 16, 16, __half, wmma::row_major> af;
            wmma::load_matrix_sync(af, e1s + (w * 32 + m * 16) * E1LD + kk * 16, E1LD);
            wmma::mma_sync(cf[0], af, bf[kk][0], cf[0]);
            wmma::mma_sync(cf[1], af, bf[kk][1], cf[1]);
        }
        wmma::store_matrix_sync(e2s + (w * 32 + m * 16) * E2LD, cf[0], E2LD, wmma::mem_row_major);
        wmma::store_matrix_sync(e2s + (w * 32 + m * 16) * E2LD + 16, cf[1], E2LD, wmma::mem_row_major);
    }
    __syncwarp();

    const float* rowp = e2s + tid * E2LD;
    float acc = b3s;
#pragma unroll
    for (int o = 0; o < 32; ++o)
        acc += W3s[o] * fmaxf(rowp[o] + b2s[o], 0.f);
    out[blockIdx.x * 128 + tid] = 1.0f / (1.0f + expf(-acc));
}

// ---------------- launch ----------------
extern "C" void kernel_launch(void* const* d_in, const int* in_sizes, int n_in,
                              void* d_out, int out_size) {
    const float* x    = (const float*)d_in[0];
    const int*   ei   = (const int*)d_in[1];
    const float* ew   = (const float*)d_in[2];
    const float* W_in = (const float*)d_in[3];
    const float* b_in = (const float*)d_in[4];
    const float* cW1  = (const float*)d_in[5];
    const float* cb1  = (const float*)d_in[6];
    const float* cW2  = (const float*)d_in[7];
    const float* cb2  = (const float*)d_in[8];
    const float* lns  = (const float*)d_in[9];
    const float* lnb  = (const float*)d_in[10];
    const float* epW1 = (const float*)d_in[11];
    const float* epb1 = (const float*)d_in[12];
    const float* epW2 = (const float*)d_in[13];
    const float* epb2 = (const float*)d_in[14];
    const float* epW3 = (const float*)d_in[15];
    const float* epb3 = (const float*)d_in[16];
    float* out = (float*)d_out;

    const int NB = (NN + 255) / 256;
    const int EB = (EE + 255) / 256;
    const int WB = NN * 32 / 256;   // exact: 6250

    zero_build_kernel<<<NB, 256>>>();
    deghist_kernel<<<EB, 256>>>(ei, ew);
    scan_kernel<<<NBLK, SCAN_BLK>>>();
    scatter_kernel<<<EB, 256>>>(ei, ew);
    inproj_kernel<<<(NN * HH) / 256, 256>>>(x, W_in, b_in);

    for (int l = 0; l < LL; ++l) {
        coeff_kernel<<<1, 128>>>(cW1 + l * 32 * CI, cb1 + l * 32,
                                 cW2 + l * (PP + 1) * 32, cb2 + l * (PP + 1));
        for (int k = 1; k < PP; ++k)
            spmm_kernel<0><<<WB, 256>>>(k, (const float*)nullptr, (const float*)nullptr,
                                        (float*)nullptr, 0);
        spmm_kernel<1><<<WB, 256>>>(PP, lns + l * HH, lnb + l * HH,
                                    (l == LL - 1) ? (out + EE) : (float*)nullptr,
                                    (l < LL - 1) ? 1 : 0);
    }

    abgemm_kernel<<<NN / 16, 256>>>(epW1);
    edge_kernel<<<EE / 128, 128>>>(ei, epb1, epW2, epb2, epW3, epb3, out);
}

// round 15
// speedup vs baseline: 1.5572x; 1.0510x over previous
#include <cuda_runtime.h>
#include <cuda_fp16.h>
#include <mma.h>
#include <math.h>

using namespace nvcuda;

#define NN 50000
#define EE 1600000
#define HH 64
#define FIN 8
#define PP 5
#define LL 3
#define CI 68   // H + 4
#define SCAN_BLK 256
#define NBLK ((NN + SCAN_BLK - 1) / SCAN_BLK)   // 196
#define NSLOT 64

// ---------------- scratch (device globals; no allocation) ----------------
__device__ __align__(128) float g_deg[NN];
__device__ __align__(128) float g_dis[NN];
__device__ __align__(128) int   g_cnt[NN];
__device__ __align__(128) int   g_fill[NN];
__device__ __align__(128) int   g_rowptr[NN + 1];
__device__ __align__(128) int   g_flag[NBLK];
__device__ __align__(128) int   g_aggval[NBLK];
__device__ __align__(128) int   g_incval[NBLK];
__device__ __align__(128) unsigned g_cw4[EE + 16];  // packed (uint16 col | half w)
__device__ __align__(128) unsigned g_eid[EE];       // original edge id per CSR slot
__device__ __align__(128) unsigned short g_r16[EE]; // row id per CSR slot
__device__ __align__(128) float g_h[NN * HH];       // fp32 master h
__device__ __align__(128) __half g_hh[NN * HH];     // fp16 mirror of h
__device__ __align__(128) __half g_tx[4][NN * HH];  // t1..t4 fp16
__device__ __align__(128) __half g_Ah[NN * HH];     // edge-pred A (fp16)
__device__ __align__(128) __half g_Bh[NN * HH];     // edge-pred B (fp16)
__device__ __align__(128) float g_pcol[NSLOT][HH];  // stats partials (coeff zeroes)
__device__ __align__(128) float g_psq[NSLOT];
__device__ float g_coeffs[PP + 1];

// packed dual-fp32 FMA (sm_103a)
__device__ __forceinline__ unsigned long long ffma2(unsigned long long a,
                                                    unsigned long long b,
                                                    unsigned long long c) {
    unsigned long long d;
    asm("fma.rn.f32x2 %0, %1, %2, %3;" : "=l"(d) : "l"(a), "l"(b), "l"(c));
    return d;
}
__device__ __forceinline__ unsigned long long pack2(float x, float y) {
    float2 t = make_float2(x, y);
    return *(unsigned long long*)&t;
}

// ---------------- graph build ----------------
__global__ void zero_build_kernel() {
    int i = blockIdx.x * blockDim.x + threadIdx.x;
    if (i < NN) { g_deg[i] = 0.f; g_cnt[i] = 0; g_fill[i] = 0; }
    if (i < NBLK) g_flag[i] = 0;
}

__global__ void deghist_kernel(const int* __restrict__ ei, const float* __restrict__ ew) {
    int e = blockIdx.x * blockDim.x + threadIdx.x;
    if (e >= EE) return;
    atomicAdd(&g_deg[ei[EE + e]], ew[e]);
    atomicAdd(&g_cnt[ei[e]], 1);
}

// single-pass scan (decoupled lookback) + dis fused
__global__ void scan_kernel() {
    __shared__ int s[SCAN_BLK];
    __shared__ int exc_s;
    int tid = threadIdx.x, b = blockIdx.x;
    int i = b * SCAN_BLK + tid;
    if (i < NN) {
        float v = rsqrtf(g_deg[i]);
        g_dis[i] = fminf(v, 1e6f);
    }
    int v = (i < NN) ? g_cnt[i] : 0;
    s[tid] = v;
    __syncthreads();
    for (int o = 1; o < SCAN_BLK; o <<= 1) {
        int t = (tid >= o) ? s[tid - o] : 0;
        __syncthreads();
        s[tid] += t;
        __syncthreads();
    }
    int agg = s[SCAN_BLK - 1];
    if (tid == 0) {
        if (b == 0) {
            g_incval[0] = agg;
            __threadfence();
            g_flag[0] = 2;
            exc_s = 0;
        } else {
            g_aggval[b] = agg;
            __threadfence();
            g_flag[b] = 1;
            int run = 0;
            for (int j = b - 1; ; --j) {
                int f;
                do { f = *(volatile int*)&g_flag[j]; } while (f == 0);
                __threadfence();
                if (f == 2) { run += *(volatile int*)&g_incval[j]; break; }
                run += *(volatile int*)&g_aggval[j];
            }
            exc_s = run;
            g_incval[b] = run + agg;
            __threadfence();
            g_flag[b] = 2;
        }
    }
    __syncthreads();
    int exc = exc_s;
    if (i < NN) g_rowptr[i] = exc + s[tid] - v;
    if (b == NBLK - 1 && tid == SCAN_BLK - 1) g_rowptr[NN] = exc + agg;
}

__global__ void scatter_kernel(const int* __restrict__ ei, const float* __restrict__ ew) {
    int e = blockIdx.x * blockDim.x + threadIdx.x;
    if (e >= EE) return;
    int r = ei[e], c = ei[EE + e];
    int pos = g_rowptr[r] + atomicAdd(&g_fill[r], 1);
    float w = g_dis[r] * ew[e] * g_dis[c];
    unsigned pk = (unsigned)c |
                  ((unsigned)__half_as_ushort(__float2half_rn(w)) << 16);
    g_cw4[pos] = pk;
    g_eid[pos] = (unsigned)e;
    g_r16[pos] = (unsigned short)r;
}

// ---------------- input projection + layer-0 stats ----------------
__global__ void __launch_bounds__(256)
inproj_kernel(const float* __restrict__ x,
              const float* __restrict__ W,
              const float* __restrict__ b) {
    __shared__ float scol[HH];
    __shared__ float ssqs;
    int tid = threadIdx.x;
    if (tid < HH) scol[tid] = 0.f;
    if (tid == 0) ssqs = 0.f;
    __syncthreads();
    int g = blockIdx.x * 256 + tid;
    float s = 0.f;
    bool ok = g < NN * HH;
    if (ok) {
        int n = g >> 6, f = g & 63;
        s = b[f];
#pragma unroll
        for (int i = 0; i < FIN; ++i) s += x[n * FIN + i] * W[f * FIN + i];
        g_h[g] = s;
        g_hh[g] = __float2half(s);
        atomicAdd(&scol[g & 63], s);
    }
    float q = ok ? s * s : 0.f;
#pragma unroll
    for (int d = 16; d; d >>= 1) q += __shfl_xor_sync(0xffffffffu, q, d);
    if ((tid & 31) == 0) atomicAdd(&ssqs, q);
    __syncthreads();
    int slot = blockIdx.x & (NSLOT - 1);
    if (tid < HH) atomicAdd(&g_pcol[slot][tid], scol[tid]);
    if (tid == 64) atomicAdd(&g_psq[slot], ssqs);
}

// ---------------- coeff MLP (consumes + rezeros stats slots) ----------------
__global__ void coeff_kernel(const float* __restrict__ cW1, const float* __restrict__ cb1,
                             const float* __restrict__ cW2, const float* __restrict__ cb2) {
    __shared__ float colsum[HH];
    __shared__ float ci[CI];
    __shared__ float hid[32];
    __shared__ float logit[PP + 1];
    __shared__ float sq_s;
    int t = threadIdx.x;
    if (t < HH) {
        float s = 0.f;
        for (int b = 0; b < NSLOT; ++b) { s += g_pcol[b][t]; g_pcol[b][t] = 0.f; }
        colsum[t] = s;
        ci[t] = s / (float)NN;
    } else if (t >= 64 && t < 96) {
        int l = t - 64;
        float s = 0.f;
        for (int b = l; b < NSLOT; b += 32) { s += g_psq[b]; g_psq[b] = 0.f; }
#pragma unroll
        for (int d = 16; d; d >>= 1) s += __shfl_xor_sync(0xffffffffu, s, d);
        if (l == 0) sq_s = s;
    }
    __syncthreads();
    if (t == 0) {
        float tot = 0.f;
        for (int i = 0; i < HH; ++i) tot += colsum[i];
        const float M = (float)NN * (float)HH;
        float mean = tot / M;
        float var  = (sq_s - tot * tot / M) / (M - 1.0f);
        ci[64] = mean;
        ci[65] = sqrtf(fmaxf(var, 0.f));
        ci[66] = (float)NN;
        ci[67] = (float)EE;
    }
    __syncthreads();
    if (t < 32) {
        float s = cb1[t];
        for (int i = 0; i < CI; ++i) s += cW1[t * CI + i] * ci[i];
        hid[t] = fmaxf(s, 0.f);
    }
    __syncthreads();
    if (t < PP + 1) {
        float s = cb2[t];
        for (int i = 0; i < 32; ++i) s += cW2[t * 32 + i] * hid[i];
        logit[t] = s;
    }
    __syncthreads();
    if (t == 0) {
        float mx = logit[0];
        for (int i = 1; i <= PP; ++i) mx = fmaxf(mx, logit[i]);
        float den = 0.f, ex[PP + 1];
        for (int i = 0; i <= PP; ++i) { ex[i] = expf(logit[i] - mx); den += ex[i]; }
        for (int i = 0; i <= PP; ++i) g_coeffs[i] = ex[i] / den;
    }
}

// ---------------- SpMM (R8 known-good): 256-thr blocks, 8/iter, unroll 2 ----------
// FUSE=1 (k==PP): residual + LayerNorm + next-layer stats, res built from t1..t4.
template <int FUSE>
__global__ void __launch_bounds__(256)
spmm_kernel(int k,
            const float* __restrict__ lnsc,
            const float* __restrict__ lnbi,
            float* outh, int do_stats) {
    __shared__ float scol[HH];
    __shared__ float ssqs;
    int tid = threadIdx.x;
    if (FUSE) {
        if (tid < HH) scol[tid] = 0.f;
        if (tid == 0) ssqs = 0.f;
        __syncthreads();
    }
    int row = (blockIdx.x * blockDim.x + tid) >> 5;   // grid exact: 50000 warps
    int lane = tid & 31;
    int sub = lane >> 3, fl = lane & 7;

    const __half* tin = (k == 1) ? g_hh : g_tx[k - 2];

    int s = g_rowptr[row], e = g_rowptr[row + 1];
    unsigned long long a0 = 0ull, a1 = 0ull, a2 = 0ull, a3 = 0ull;

#pragma unroll 2
    for (int jb = s; jb < e; jb += 8) {
        int jA = jb + sub, jB = jb + 4 + sub;
        unsigned cwA = __ldg(&g_cw4[jA]);
        unsigned cwB = __ldg(&g_cw4[jB]);
        int colA = (jA < e) ? (int)(cwA & 0xFFFFu) : 0;
        float wA  = (jA < e) ? __half2float(__ushort_as_half((unsigned short)(cwA >> 16))) : 0.f;
        int colB = (jB < e) ? (int)(cwB & 0xFFFFu) : 0;
        float wB  = (jB < e) ? __half2float(__ushort_as_half((unsigned short)(cwB >> 16))) : 0.f;
        uint4 dA = __ldg((const uint4*)tin + colA * 8 + fl);
        uint4 dB = __ldg((const uint4*)tin + colB * 8 + fl);
        unsigned long long wpA = pack2(wA, wA);
        unsigned long long wpB = pack2(wB, wB);
        const __half2* hpA = (const __half2*)&dA;
        const __half2* hpB = (const __half2*)&dB;
        float2 vA0 = __half22float2(hpA[0]), vA1 = __half22float2(hpA[1]);
        float2 vA2 = __half22float2(hpA[2]), vA3 = __half22float2(hpA[3]);
        float2 vB0 = __half22float2(hpB[0]), vB1 = __half22float2(hpB[1]);
        float2 vB2 = __half22float2(hpB[2]), vB3 = __half22float2(hpB[3]);
        a0 = ffma2(wpA, *(unsigned long long*)&vA0, a0);
        a1 = ffma2(wpA, *(unsigned long long*)&vA1, a1);
        a2 = ffma2(wpA, *(unsigned long long*)&vA2, a2);
        a3 = ffma2(wpA, *(unsigned long long*)&vA3, a3);
        a0 = ffma2(wpB, *(unsigned long long*)&vB0, a0);
        a1 = ffma2(wpB, *(unsigned long long*)&vB1, a1);
        a2 = ffma2(wpB, *(unsigned long long*)&vB2, a2);
        a3 = ffma2(wpB, *(unsigned long long*)&vB3, a3);
    }

    float t[8];
    { float2 f0 = *(float2*)&a0, f1 = *(float2*)&a1, f2 = *(float2*)&a2, f3 = *(float2*)&a3;
      t[0]=f0.x; t[1]=f0.y; t[2]=f1.x; t[3]=f1.y; t[4]=f2.x; t[5]=f2.y; t[6]=f3.x; t[7]=f3.y; }
#pragma unroll
    for (int i = 0; i < 8; ++i) {
        t[i] += __shfl_xor_sync(0xffffffffu, t[i], 8);
        t[i] += __shfl_xor_sync(0xffffffffu, t[i], 16);
    }

    if (!FUSE) {
        if (sub == 0) {
            __half2 o0 = __floats2half2_rn(t[0], t[1]);
            __half2 o1 = __floats2half2_rn(t[2], t[3]);
            __half2 o2 = __floats2half2_rn(t[4], t[5]);
            __half2 o3 = __floats2half2_rn(t[6], t[7]);
            ((uint4*)g_tx[k - 1])[row * 8 + fl] =
                make_uint4(*(unsigned*)&o0, *(unsigned*)&o1, *(unsigned*)&o2, *(unsigned*)&o3);
        }
    } else {
        float c0 = g_coeffs[0], c1 = g_coeffs[1], c2 = g_coeffs[2];
        float c3 = g_coeffs[3], c4 = g_coeffs[4], c5 = g_coeffs[5];
        float4 h0 = __ldg((const float4*)g_h + row * 16 + fl * 2);
        float4 h1 = __ldg((const float4*)g_h + row * 16 + fl * 2 + 1);
        uint4 x1 = __ldg((const uint4*)g_tx[0] + row * 8 + fl);
        uint4 x2 = __ldg((const uint4*)g_tx[1] + row * 8 + fl);
        uint4 x3 = __ldg((const uint4*)g_tx[2] + row * 8 + fl);
        uint4 x4 = __ldg((const uint4*)g_tx[3] + row * 8 + fl);
        const __half2 *p1 = (const __half2*)&x1, *p2 = (const __half2*)&x2;
        const __half2 *p3 = (const __half2*)&x3, *p4 = (const __half2*)&x4;
        float hv[8], v[8];
        hv[0]=h0.x; hv[1]=h0.y; hv[2]=h0.z; hv[3]=h0.w;
        hv[4]=h1.x; hv[5]=h1.y; hv[6]=h1.z; hv[7]=h1.w;
#pragma unroll
        for (int i = 0; i < 4; ++i) {
            float2 t1v = __half22float2(p1[i]);
            float2 t2v = __half22float2(p2[i]);
            float2 t3v = __half22float2(p3[i]);
            float2 t4v = __half22float2(p4[i]);
            float rx = c0*hv[2*i] + c1*t1v.x + c2*t2v.x + c3*t3v.x + c4*t4v.x + c5*t[2*i];
            float ry = c0*hv[2*i+1] + c1*t1v.y + c2*t2v.y + c3*t3v.y + c4*t4v.y + c5*t[2*i+1];
            v[2*i]   = hv[2*i] + rx;
            v[2*i+1] = hv[2*i+1] + ry;
        }
        float ps = 0.f;
#pragma unroll
        for (int i = 0; i < 8; ++i) ps += v[i];
#pragma unroll
        for (int d = 1; d <= 4; d <<= 1) ps += __shfl_xor_sync(0xffffffffu, ps, d);
        float m = ps * (1.0f / HH);
        float q = 0.f;
#pragma unroll
        for (int i = 0; i < 8; ++i) { v[i] -= m; q += v[i] * v[i]; }
#pragma unroll
        for (int d = 1; d <= 4; d <<= 1) q += __shfl_xor_sync(0xffffffffu, q, d);
        float inv = rsqrtf(q * (1.0f / HH) + 1e-5f);
        float4 s0 = __ldg((const float4*)lnsc + fl * 2);
        float4 s1 = __ldg((const float4*)lnsc + fl * 2 + 1);
        float4 b0 = __ldg((const float4*)lnbi + fl * 2);
        float4 b1 = __ldg((const float4*)lnbi + fl * 2 + 1);
        float o[8];
        o[0]=v[0]*inv*s0.x+b0.x; o[1]=v[1]*inv*s0.y+b0.y;
        o[2]=v[2]*inv*s0.z+b0.z; o[3]=v[3]*inv*s0.w+b0.w;
        o[4]=v[4]*inv*s1.x+b1.x; o[5]=v[5]*inv*s1.y+b1.y;
        o[6]=v[6]*inv*s1.z+b1.z; o[7]=v[7]*inv*s1.w+b1.w;
        if (sub == 0) {
            float4 w0 = make_float4(o[0],o[1],o[2],o[3]);
            float4 w1 = make_float4(o[4],o[5],o[6],o[7]);
            ((float4*)g_h)[row * 16 + fl * 2]     = w0;
            ((float4*)g_h)[row * 16 + fl * 2 + 1] = w1;
            __half2 q0 = __floats2half2_rn(o[0],o[1]);
            __half2 q1 = __floats2half2_rn(o[2],o[3]);
            __half2 q2 = __floats2half2_rn(o[4],o[5]);
            __half2 q3 = __floats2half2_rn(o[6],o[7]);
            ((uint4*)g_hh)[row * 8 + fl] = make_uint4(*(unsigned*)&q0, *(unsigned*)&q1,
                                                      *(unsigned*)&q2, *(unsigned*)&q3);
            if (outh) {
                ((float4*)outh)[row * 16 + fl * 2]     = w0;
                ((float4*)outh)[row * 16 + fl * 2 + 1] = w1;
            }
        }
        if (do_stats) {
            if (sub == 0) {
#pragma unroll
                for (int i = 0; i < 8; ++i) atomicAdd(&scol[fl * 8 + i], o[i]);
            }
            float so = 0.f;
#pragma unroll
            for (int i = 0; i < 8; ++i) so += o[i] * o[i];
#pragma unroll
            for (int d = 1; d <= 4; d <<= 1) so += __shfl_xor_sync(0xffffffffu, so, d);
            if (lane == 0) atomicAdd(&ssqs, so);
            __syncthreads();
            int slot = blockIdx.x & (NSLOT - 1);
            if (tid < HH) atomicAdd(&g_pcol[slot][tid], scol[tid]);
            if (tid == 64) atomicAdd(&g_psq[slot], ssqs);
        }
    }
}

// ---------------- edge predictor A/B: 16 nodes per 256-thr block ----------------
__global__ void __launch_bounds__(256)
abgemm_kernel(const float* __restrict__ epW1) {
    __shared__ float WtA[64 * 64];
    __shared__ float WtB[64 * 64];
    __shared__ float hs[16 * 64];
    int tid = threadIdx.x;
    for (int idx = tid; idx < 4096; idx += 256) {
        int f = idx >> 6, i = idx & 63;
        WtA[i * 64 + f] = epW1[f * 128 + i];
        WtB[i * 64 + f] = epW1[f * 128 + 64 + i];
    }
    int n0 = blockIdx.x * 16;
    for (int idx = tid; idx < 16 * 64; idx += 256)
        hs[idx] = g_h[n0 * 64 + idx];
    __syncthreads();
#pragma unroll
    for (int rep = 0; rep < 4; ++rep) {
        int oidx = rep * 256 + tid;
        int ln = oidx >> 6, f = oidx & 63;
        float a = 0.f, b = 0.f;
#pragma unroll
        for (int i = 0; i < 64; ++i) {
            float hv = hs[ln * 64 + i];
            a += hv * WtA[i * 64 + f];
            b += hv * WtB[i * 64 + f];
        }
        g_Ah[(n0 + ln) * 64 + f] = __float2half(a);
        g_Bh[(n0 + ln) * 64 + f] = __float2half(b);
    }
}

// ---------------- edge kernel v3: CSR-ordered, 4 tiles/block, wmma layer 2 --------
#define E1LD 72   // padded half stride
#define E2LD 36   // padded float stride
__global__ void __launch_bounds__(128)
edge_kernel(const float* __restrict__ epb1,
            const float* __restrict__ epW2, const float* __restrict__ epb2,
            const float* __restrict__ epW3, const float* __restrict__ epb3,
            float* __restrict__ out) {
    __shared__ __half e1s[128 * E1LD];
    __shared__ __half W2h[32 * 64];
    __shared__ float  e2s[128 * E2LD];
    __shared__ float  b2s[32], W3s[32];
    __shared__ float  b3s;
    int tid = threadIdx.x;
    int w = tid >> 5, lane = tid & 31, sub = lane >> 3, fl = lane & 7;
    for (int idx = tid; idx < 2048; idx += 128) W2h[idx] = __float2half(epW2[idx]);
    if (tid < 32) { b2s[tid] = epb2[tid]; W3s[tid] = epW3[tid]; }
    if (tid == 0) b3s = epb3[0];
    __syncthreads();

    float4 bb0 = __ldg((const float4*)epb1 + fl * 2);
    float4 bb1 = __ldg((const float4*)epb1 + fl * 2 + 1);
    float2 bias[4] = { make_float2(bb0.x, bb0.y), make_float2(bb0.z, bb0.w),
                       make_float2(bb1.x, bb1.y), make_float2(bb1.z, bb1.w) };

    // load W2 fragments once for all 4 tiles
    wmma::fragment<wmma::matrix_b, 16, 16, 16, __half, wmma::col_major> bf[4][2];
#pragma unroll
    for (int kk = 0; kk < 4; ++kk)
#pragma unroll
        for (int n = 0; n < 2; ++n)
            wmma::load_matrix_sync(bf[kk][n], W2h + n * 16 * 64 + kk * 16, 64);

#pragma unroll
    for (int tile = 0; tile < 4; ++tile) {
        int base = blockIdx.x * 512 + tile * 128 + w * 32;   // CSR slot base for this warp
        int slot = base + lane;
        int r_own = (int)g_r16[slot];
        int c_own = (int)(__ldg(&g_cw4[slot]) & 0xFFFFu);
        unsigned eid_own = g_eid[slot];

        // phase A: 4 edges/step, 8 lanes/edge; A[r] loads are L1-local (CSR order)
#pragma unroll
        for (int step = 0; step < 8; ++step) {
            int idx = step * 4 + sub;
            int rj = __shfl_sync(0xffffffffu, r_own, idx);
            int cj = __shfl_sync(0xffffffffu, c_own, idx);
            uint4 a4 = __ldg((const uint4*)g_Ah + rj * 8 + fl);
            uint4 b4 = __ldg((const uint4*)g_Bh + cj * 8 + fl);
            const __half2* ap = (const __half2*)&a4;
            const __half2* bp = (const __half2*)&b4;
            int e_local = w * 32 + idx;
#pragma unroll
            for (int kk = 0; kk < 4; ++kk) {
                float2 av = __half22float2(ap[kk]);
                float2 bv = __half22float2(bp[kk]);
                float vx = fmaxf(av.x + bv.x + bias[kk].x, 0.f);
                float vy = fmaxf(av.y + bv.y + bias[kk].y, 0.f);
                *(__half2*)(e1s + e_local * E1LD + (fl * 4 + kk) * 2) = __floats2half2_rn(vx, vy);
            }
        }
        __syncwarp();

        // phase B: wmma over this warp's 32 edges
#pragma unroll
        for (int m = 0; m < 2; ++m) {
            wmma::fragment<wmma::accumulator, 16, 16, 16, float> cf[2];
            wmma::fill_fragment(cf[0], 0.f);
            wmma::fill_fragment(cf[1], 0.f);
#pragma unroll
            for (int kk = 0; kk < 4; ++kk) {
                wmma::fragment<wmma::matrix_a, 16, 16, 16, __half, wmma::row_major> af;
                wmma::load_matrix_sync(af, e1s + (w * 32 + m * 16) * E1LD + kk * 16, E1LD);
                wmma::mma_sync(cf[0], af, bf[kk][0], cf[0]);
                wmma::mma_sync(cf[1], af, bf[kk][1], cf[1]);
            }
            wmma::store_matrix_sync(e2s + (w * 32 + m * 16) * E2LD, cf[0], E2LD, wmma::mem_row_major);
            wmma::store_matrix_sync(e2s + (w * 32 + m * 16) * E2LD + 16, cf[1], E2LD, wmma::mem_row_major);
        }
        __syncwarp();

        // phase C: lane per edge readout, scattered store to original edge id
        const float* rowp = e2s + (w * 32 + lane) * E2LD;
        float acc = b3s;
#pragma unroll
        for (int o = 0; o < 32; ++o)
            acc += W3s[o] * fmaxf(rowp[o] + b2s[o], 0.f);
        out[eid_own] = 1.0f / (1.0f + expf(-acc));
        __syncwarp();
    }
}

// ---------------- launch ----------------
extern "C" void kernel_launch(void* const* d_in, const int* in_sizes, int n_in,
                              void* d_out, int out_size) {
    const float* x    = (const float*)d_in[0];
    const int*   ei   = (const int*)d_in[1];
    const float* ew   = (const float*)d_in[2];
    const float* W_in = (const float*)d_in[3];
    const float* b_in = (const float*)d_in[4];
    const float* cW1  = (const float*)d_in[5];
    const float* cb1  = (const float*)d_in[6];
    const float* cW2  = (const float*)d_in[7];
    const float* cb2  = (const float*)d_in[8];
    const float* lns  = (const float*)d_in[9];
    const float* lnb  = (const float*)d_in[10];
    const float* epW1 = (const float*)d_in[11];
    const float* epb1 = (const float*)d_in[12];
    const float* epW2 = (const float*)d_in[13];
    const float* epb2 = (const float*)d_in[14];
    const float* epW3 = (const float*)d_in[15];
    const float* epb3 = (const float*)d_in[16];
    float* out = (float*)d_out;

    const int NB = (NN + 255) / 256;
    const int EB = (EE + 255) / 256;
    const int WB = NN * 32 / 256;   // exact: 6250

    zero_build_kernel<<<NB, 256>>>();
    deghist_kernel<<<EB, 256>>>(ei, ew);
    scan_kernel<<<NBLK, SCAN_BLK>>>();
    scatter_kernel<<<EB, 256>>>(ei, ew);
    inproj_kernel<<<(NN * HH) / 256, 256>>>(x, W_in, b_in);

    for (int l = 0; l < LL; ++l) {
        coeff_kernel<<<1, 128>>>(cW1 + l * 32 * CI, cb1 + l * 32,
                                 cW2 + l * (PP + 1) * 32, cb2 + l * (PP + 1));
        for (int k = 1; k < PP; ++k)
            spmm_kernel<0><<<WB, 256>>>(k, (const float*)nullptr, (const float*)nullptr,
                                        (float*)nullptr, 0);
        spmm_kernel<1><<<WB, 256>>>(PP, lns + l * HH, lnb + l * HH,
                                    (l == LL - 1) ? (out + EE) : (float*)nullptr,
                                    (l < LL - 1) ? 1 : 0);
    }

    abgemm_kernel<<<NN / 16, 256>>>(epW1);
    edge_kernel<<<EE / 512, 128>>>(epb1, epW2, epb2, epW3, epb3, out);
}